// round 4
// baseline (speedup 1.0000x reference)
#include <cuda_runtime.h>
#include <math.h>

#define NSEG 1024
#define NPIX (512 * 512)
#define NCH  21
#define NB   4

// Scratch (no allocations allowed)
__device__ float  g_seg_sum[NB * NSEG];
__device__ int    g_cnt[NB * NSEG];
__device__ float  g_m[NB * NSEG];
__device__ double g_quad[NB];
__device__ double g_w2[NB];
__device__ int    g_is64;

__global__ void k_zero() {
    int i = blockIdx.x * blockDim.x + threadIdx.x;
    if (i < NB * NSEG) { g_seg_sum[i] = 0.f; g_cnt[i] = 0; }
    if (i < NB) { g_quad[i] = 0.0; g_w2[i] = 0.0; }
}

// Deterministic dtype probe: int64 ids (values in [0,1024)) have all odd
// 32-bit words == 0; int32 ids have random ids there. Reads only the first
// 1 KB of the buffer — in bounds for either dtype.
__global__ void k_detect(const unsigned int* __restrict__ ids_raw) {
    if (threadIdx.x == 0 && blockIdx.x == 0) {
        int all_zero = 1;
        #pragma unroll 1
        for (int i = 1; i < 256; i += 2)
            if (ids_raw[i] != 0u) { all_zero = 0; break; }
        g_is64 = all_zero;
    }
}

// Histogram: per-pixel channel sum -> shared 1024-bin accumulation -> global flush
// grid: (64, NB), block: 256  => 4096 pixels/block
__global__ void k_hist(const float* __restrict__ pred,
                       const void* __restrict__ ids_v) {
    __shared__ float s_sum[NSEG];
    __shared__ int   s_cnt[NSEG];
    const int b = blockIdx.y;
    for (int i = threadIdx.x; i < NSEG; i += blockDim.x) { s_sum[i] = 0.f; s_cnt[i] = 0; }
    __syncthreads();

    const int is64 = g_is64;
    const float* __restrict__ p0 = pred + (size_t)b * NCH * NPIX;
    const int*       id32 = (const int*)ids_v + (size_t)b * NPIX;
    const long long* id64 = (const long long*)ids_v + (size_t)b * NPIX;

    const int pix_per_block = NPIX / gridDim.x;      // 4096
    const int base = blockIdx.x * pix_per_block;

    for (int p = base + threadIdx.x; p < base + pix_per_block; p += blockDim.x) {
        float s = 0.f;
        #pragma unroll
        for (int c = 0; c < NCH; ++c)
            s += p0[(size_t)c * NPIX + p];           // coalesced, 21-way MLP
        int id = is64 ? (int)id64[p] : id32[p];
        id &= (NSEG - 1);                            // safety clamp
        atomicAdd(&s_sum[id], s);
        atomicAdd(&s_cnt[id], 1);
    }
    __syncthreads();

    for (int i = threadIdx.x; i < NSEG; i += blockDim.x) {
        if (s_cnt[i] != 0) {
            atomicAdd(&g_seg_sum[b * NSEG + i], s_sum[i]);
            atomicAdd(&g_cnt[b * NSEG + i], s_cnt[i]);
        }
    }
}

__global__ void k_mean() {
    int i = blockIdx.x * blockDim.x + threadIdx.x;
    if (i < NB * NSEG) {
        int c = g_cnt[i];
        g_m[i] = (c > 0) ? g_seg_sum[i] / (float)c : 0.f;
    }
}

// quad[b] = m^T L m. grid: (128, NB), block: 256 (8 warps -> 8 rows/block)
__global__ void k_quad(const float* __restrict__ L) {
    __shared__ float s_m[NSEG];
    const int b = blockIdx.y;
    for (int i = threadIdx.x; i < NSEG; i += blockDim.x)
        s_m[i] = g_m[b * NSEG + i];
    __syncthreads();

    const int warp = threadIdx.x >> 5;
    const int lane = threadIdx.x & 31;
    const int rows_per_block = NSEG / gridDim.x;     // 8
    const int nwarps = blockDim.x >> 5;              // 8

    const float4* __restrict__ sm4 = (const float4*)s_m;
    double acc = 0.0;

    for (int r = blockIdx.x * rows_per_block + warp;
         r < (blockIdx.x + 1) * rows_per_block; r += nwarps) {
        const float4* __restrict__ Lr =
            (const float4*)(L + (size_t)b * NSEG * NSEG + (size_t)r * NSEG);
        float s = 0.f;
        #pragma unroll
        for (int i = 0; i < NSEG / 128; ++i) {       // 8 iters
            int c4 = i * 32 + lane;                  // float4 index
            float4 l4 = Lr[c4];
            float4 m4 = sm4[c4];
            s += l4.x * m4.x + l4.y * m4.y + l4.z * m4.z + l4.w * m4.w;
        }
        #pragma unroll
        for (int o = 16; o > 0; o >>= 1)
            s += __shfl_xor_sync(0xffffffffu, s, o);
        if (lane == 0)
            acc += (double)s * (double)s_m[r];
    }
    if (lane == 0)
        atomicAdd(&g_quad[b], acc);
}

// ||W||_F^2 per batch. grid: (64, NB), block: 256
__global__ void k_w2(const float* __restrict__ W) {
    const int b = blockIdx.y;
    const float4* __restrict__ Wb =
        (const float4*)(W + (size_t)b * NSEG * NSEG);
    const int n4 = NSEG * NSEG / 4;

    float s = 0.f;
    for (int i = blockIdx.x * blockDim.x + threadIdx.x; i < n4;
         i += gridDim.x * blockDim.x) {
        float4 v = Wb[i];
        s += v.x * v.x + v.y * v.y + v.z * v.z + v.w * v.w;
    }
    __shared__ float red[256];
    red[threadIdx.x] = s;
    __syncthreads();
    for (int off = 128; off > 0; off >>= 1) {
        if (threadIdx.x < off) red[threadIdx.x] += red[threadIdx.x + off];
        __syncthreads();
    }
    if (threadIdx.x == 0)
        atomicAdd(&g_w2[b], (double)red[0]);
}

__global__ void k_final(float* __restrict__ out) {
    if (threadIdx.x == 0 && blockIdx.x == 0) {
        double loss = 0.0;
        #pragma unroll
        for (int b = 0; b < NB; ++b)
            loss += (2.0 / sqrt(g_w2[b])) * ((double)NCH * g_quad[b]);
        out[0] = (float)loss;
    }
}

extern "C" void kernel_launch(void* const* d_in, const int* in_sizes, int n_in,
                              void* d_out, int out_size) {
    const float* pred = (const float*)d_in[0];
    const float* W    = (const float*)d_in[1];
    const float* L    = (const float*)d_in[2];
    const void*  ids  = (const void*)d_in[3];
    float* out = (float*)d_out;

    k_zero<<<16, 256>>>();
    k_detect<<<1, 32>>>((const unsigned int*)ids);
    k_hist<<<dim3(64, NB), 256>>>(pred, ids);
    k_mean<<<16, 256>>>();
    k_quad<<<dim3(128, NB), 256>>>(L);
    k_w2<<<dim3(64, NB), 256>>>(W);
    k_final<<<1, 32>>>(out);
}

// round 5
// speedup vs baseline: 1.1956x; 1.1956x over previous
#include <cuda_runtime.h>
#include <math.h>

#define NSEG 1024
#define NPIX (512 * 512)
#define NCH  21
#define NB   4
#define HB   128           // hist x-blocks per batch

// Scratch (no allocations allowed). Partials are fully overwritten -> no zeroing.
__device__ float  g_part_sum[NB * HB * NSEG];   // 2 MB
__device__ int    g_part_cnt[NB * HB * NSEG];   // 2 MB
__device__ float  g_m[NB * NSEG];
__device__ double g_quad[NB];
__device__ double g_w2[NB];
__device__ unsigned int g_done;

// ---------------------------------------------------------------------------
// Kernel 1: histogram. grid (HB, NB) x 256. 4 pixels/thread via float4.
// Per-block dtype probe (int64 ids have all odd 32-bit words == 0).
// Writes per-block partials to dedicated slots (no atomics, no pre-zero).
// ---------------------------------------------------------------------------
__global__ __launch_bounds__(256) void k_hist(const float* __restrict__ pred,
                                              const void* __restrict__ ids_v) {
    __shared__ float s_sum[NSEG];
    __shared__ int   s_cnt[NSEG];
    __shared__ int   s_nonzero;

    const int tid = threadIdx.x;
    const int b   = blockIdx.y;

    if (tid == 0) s_nonzero = 0;
    for (int i = tid; i < NSEG; i += 256) { s_sum[i] = 0.f; s_cnt[i] = 0; }
    __syncthreads();

    // dtype probe: first 1 KB of ids buffer (in bounds either way, L2-hot)
    if (tid < 128 && ((const unsigned int*)ids_v)[2 * tid + 1] != 0u)
        atomicOr(&s_nonzero, 1);
    __syncthreads();
    const int is64 = !s_nonzero;

    const float4* __restrict__ p4 =
        (const float4*)(pred + (size_t)b * NCH * NPIX);
    const int4* __restrict__ id32v =
        (const int4*)((const int*)ids_v + (size_t)b * NPIX);
    const longlong2* __restrict__ id64v =
        (const longlong2*)((const long long*)ids_v + (size_t)b * NPIX);

    const int q_per_block = NPIX / 4 / HB;          // 512 float4 groups
    const int qbase = blockIdx.x * q_per_block;

    for (int q = qbase + tid; q < qbase + q_per_block; q += 256) {
        float4 acc = make_float4(0.f, 0.f, 0.f, 0.f);
        #pragma unroll
        for (int c = 0; c < NCH; ++c) {
            float4 v = p4[(size_t)c * (NPIX / 4) + q];
            acc.x += v.x; acc.y += v.y; acc.z += v.z; acc.w += v.w;
        }
        int i0, i1, i2, i3;
        if (is64) {
            longlong2 a = id64v[2 * q];
            longlong2 c = id64v[2 * q + 1];
            i0 = (int)a.x; i1 = (int)a.y; i2 = (int)c.x; i3 = (int)c.y;
        } else {
            int4 iv = id32v[q];
            i0 = iv.x; i1 = iv.y; i2 = iv.z; i3 = iv.w;
        }
        atomicAdd(&s_sum[i0 & (NSEG - 1)], acc.x); atomicAdd(&s_cnt[i0 & (NSEG - 1)], 1);
        atomicAdd(&s_sum[i1 & (NSEG - 1)], acc.y); atomicAdd(&s_cnt[i1 & (NSEG - 1)], 1);
        atomicAdd(&s_sum[i2 & (NSEG - 1)], acc.z); atomicAdd(&s_cnt[i2 & (NSEG - 1)], 1);
        atomicAdd(&s_sum[i3 & (NSEG - 1)], acc.w); atomicAdd(&s_cnt[i3 & (NSEG - 1)], 1);
    }
    __syncthreads();

    const size_t slot = (size_t)(b * HB + blockIdx.x) * NSEG;
    for (int i = tid; i < NSEG; i += 256) {
        g_part_sum[slot + i] = s_sum[i];
        g_part_cnt[slot + i] = s_cnt[i];
    }
}

// ---------------------------------------------------------------------------
// Kernel 2: reduce partials -> g_m; zero the fused-kernel accumulators.
// grid 16 x 256 (one thread per (b, bin)).
// ---------------------------------------------------------------------------
__global__ __launch_bounds__(256) void k_mid() {
    int gid = blockIdx.x * blockDim.x + threadIdx.x;   // 0 .. NB*NSEG-1
    if (gid < NB) g_quad[gid] = 0.0;
    if (gid >= NB && gid < 2 * NB) g_w2[gid - NB] = 0.0;
    if (gid == 2 * NB) g_done = 0u;

    const int b  = gid >> 10;
    const int lb = gid & (NSEG - 1);
    float sum = 0.f;
    int   cnt = 0;
    #pragma unroll 8
    for (int p = 0; p < HB; ++p) {
        size_t idx = (size_t)(b * HB + p) * NSEG + lb;
        sum += g_part_sum[idx];
        cnt += g_part_cnt[idx];
    }
    g_m[gid] = (cnt > 0) ? sum / (float)cnt : 0.f;
}

// ---------------------------------------------------------------------------
// Kernel 3: fused quad (x < 128) + ||W||^2 (x >= 128) + final (last block).
// grid (160, NB) x 256.
// ---------------------------------------------------------------------------
#define QX 128
#define WX 32
#define TOTAL_BLOCKS ((QX + WX) * NB)

__global__ __launch_bounds__(256) void k_qw(const float* __restrict__ L,
                                            const float* __restrict__ W,
                                            float* __restrict__ out) {
    const int b    = blockIdx.y;
    const int tid  = threadIdx.x;
    const int warp = tid >> 5;
    const int lane = tid & 31;

    if (blockIdx.x < QX) {
        // ---- quad: 8 warps -> 8 rows of L ----
        __shared__ float s_m[NSEG];
        for (int i = tid; i < NSEG; i += 256) s_m[i] = g_m[b * NSEG + i];
        __syncthreads();

        const int r = blockIdx.x * 8 + warp;
        const float4* __restrict__ Lr =
            (const float4*)(L + (size_t)b * NSEG * NSEG + (size_t)r * NSEG);
        const float4* __restrict__ sm4 = (const float4*)s_m;

        float s = 0.f;
        #pragma unroll
        for (int i = 0; i < NSEG / 128; ++i) {        // 8 iters of float4
            int c4 = i * 32 + lane;
            float4 l4 = Lr[c4];
            float4 m4 = sm4[c4];
            s += l4.x * m4.x + l4.y * m4.y + l4.z * m4.z + l4.w * m4.w;
        }
        #pragma unroll
        for (int o = 16; o > 0; o >>= 1)
            s += __shfl_xor_sync(0xffffffffu, s, o);
        if (lane == 0)
            atomicAdd(&g_quad[b], (double)s * (double)s_m[r]);
    } else {
        // ---- ||W||_F^2 chunk ----
        const int cx = blockIdx.x - QX;               // 0..31
        const int n4_per_chunk = (NSEG * NSEG / 4) / WX;  // 8192
        const float4* __restrict__ Wb =
            (const float4*)(W + (size_t)b * NSEG * NSEG) + (size_t)cx * n4_per_chunk;

        float s = 0.f;
        for (int i = tid; i < n4_per_chunk; i += 256) {
            float4 v = Wb[i];
            s += v.x * v.x + v.y * v.y + v.z * v.z + v.w * v.w;
        }
        #pragma unroll
        for (int o = 16; o > 0; o >>= 1)
            s += __shfl_xor_sync(0xffffffffu, s, o);
        __shared__ float red[8];
        if (lane == 0) red[warp] = s;
        __syncthreads();
        if (tid == 0) {
            float t = 0.f;
            #pragma unroll
            for (int w = 0; w < 8; ++w) t += red[w];
            atomicAdd(&g_w2[b], (double)t);
        }
    }

    // ---- completion: last block computes the output ----
    __syncthreads();
    if (tid == 0) {
        __threadfence();
        unsigned int prev = atomicAdd(&g_done, 1u);
        if (prev == TOTAL_BLOCKS - 1) {
            __threadfence();
            double loss = 0.0;
            #pragma unroll
            for (int k = 0; k < NB; ++k)
                loss += (2.0 / sqrt(g_w2[k])) * ((double)NCH * g_quad[k]);
            out[0] = (float)loss;
        }
    }
}

extern "C" void kernel_launch(void* const* d_in, const int* in_sizes, int n_in,
                              void* d_out, int out_size) {
    const float* pred = (const float*)d_in[0];
    const float* W    = (const float*)d_in[1];
    const float* L    = (const float*)d_in[2];
    const void*  ids  = (const void*)d_in[3];
    float* out = (float*)d_out;

    k_hist<<<dim3(HB, NB), 256>>>(pred, ids);
    k_mid<<<(NB * NSEG) / 256, 256>>>();
    k_qw<<<dim3(QX + WX, NB), 256>>>(L, W, out);
}

// round 6
// speedup vs baseline: 1.3090x; 1.0948x over previous
#include <cuda_runtime.h>
#include <math.h>

#define NSEG 1024
#define NPIX (512 * 512)
#define NCH  21
#define NB   4
#define HB   128           // hist x-blocks per batch
#define WX   32            // W^2 x-blocks per batch
#define QX   128           // quad x-blocks per batch
#define K3_TOTAL (QX * NB)

// Scratch (no allocations). Slot-overwritten or zeroed in K1 before use.
__device__ float2 g_part2[NB * HB * NSEG];   // hist per-block (sum, cnt) — overwritten
__device__ double g_w2p[NB * WX];            // W^2 per-block partials — overwritten
__device__ float  g_msum[NB * NSEG];         // zeroed in K1, atomics in K2
__device__ float  g_mcnt[NB * NSEG];         // zeroed in K1, atomics in K2
__device__ double g_w2[NB];                  // written (overwrite) in K2
__device__ double g_quad[NB];                // zeroed in K1, atomics in K3
__device__ unsigned int g_done;              // zeroed in K1, counter in K3

// ---------------------------------------------------------------------------
// K1: grid (HB+WX, NB) x 512.
//   x < HB  : histogram (shared 1024-bin, float4 pred, per-block partial slots)
//   x >= HB : ||W||^2 chunk -> g_w2p slot; chunk 0 also zeroes accumulators
// ---------------------------------------------------------------------------
__global__ __launch_bounds__(512) void k1(const float* __restrict__ pred,
                                          const void* __restrict__ ids_v,
                                          const float* __restrict__ W) {
    const int tid = threadIdx.x;
    const int b   = blockIdx.y;

    if (blockIdx.x < HB) {
        __shared__ float s_sum[NSEG];
        __shared__ int   s_cnt[NSEG];
        __shared__ int   s_nonzero;

        if (tid == 0) s_nonzero = 0;
        for (int i = tid; i < NSEG; i += 512) { s_sum[i] = 0.f; s_cnt[i] = 0; }
        __syncthreads();

        // dtype probe: int64 ids in [0,1024) -> all odd 32-bit words zero.
        if (tid < 128 && ((const unsigned int*)ids_v)[2 * tid + 1] != 0u)
            atomicOr(&s_nonzero, 1);
        __syncthreads();
        const int is64 = !s_nonzero;

        const float4* __restrict__ p4 =
            (const float4*)(pred + (size_t)b * NCH * NPIX);
        const int4* __restrict__ id32v =
            (const int4*)((const int*)ids_v + (size_t)b * NPIX);
        const longlong2* __restrict__ id64v =
            (const longlong2*)((const long long*)ids_v + (size_t)b * NPIX);

        const int q = blockIdx.x * 512 + tid;        // one float4-group/thread
        float4 acc = make_float4(0.f, 0.f, 0.f, 0.f);
        #pragma unroll
        for (int c = 0; c < NCH; ++c) {
            float4 v = p4[(size_t)c * (NPIX / 4) + q];
            acc.x += v.x; acc.y += v.y; acc.z += v.z; acc.w += v.w;
        }
        int i0, i1, i2, i3;
        if (is64) {
            longlong2 a = id64v[2 * q];
            longlong2 c = id64v[2 * q + 1];
            i0 = (int)a.x; i1 = (int)a.y; i2 = (int)c.x; i3 = (int)c.y;
        } else {
            int4 iv = id32v[q];
            i0 = iv.x; i1 = iv.y; i2 = iv.z; i3 = iv.w;
        }
        atomicAdd(&s_sum[i0 & (NSEG - 1)], acc.x); atomicAdd(&s_cnt[i0 & (NSEG - 1)], 1);
        atomicAdd(&s_sum[i1 & (NSEG - 1)], acc.y); atomicAdd(&s_cnt[i1 & (NSEG - 1)], 1);
        atomicAdd(&s_sum[i2 & (NSEG - 1)], acc.z); atomicAdd(&s_cnt[i2 & (NSEG - 1)], 1);
        atomicAdd(&s_sum[i3 & (NSEG - 1)], acc.w); atomicAdd(&s_cnt[i3 & (NSEG - 1)], 1);
        __syncthreads();

        float2* __restrict__ slot =
            g_part2 + (size_t)(b * HB + blockIdx.x) * NSEG;
        for (int i = tid; i < NSEG; i += 512)
            slot[i] = make_float2(s_sum[i], (float)s_cnt[i]);
    } else {
        const int cx = blockIdx.x - HB;               // 0..WX-1

        // chunk 0 zeroes next-stage accumulators for this batch
        if (cx == 0) {
            for (int i = tid; i < NSEG; i += 512) {
                g_msum[b * NSEG + i] = 0.f;
                g_mcnt[b * NSEG + i] = 0.f;
            }
            if (tid == 0) {
                g_quad[b] = 0.0;
                if (b == 0) g_done = 0u;
            }
        }

        const int n4_per_chunk = (NSEG * NSEG / 4) / WX;  // 8192
        const float4* __restrict__ Wb =
            (const float4*)(W + (size_t)b * NSEG * NSEG) + (size_t)cx * n4_per_chunk;

        float s = 0.f;
        for (int i = tid; i < n4_per_chunk; i += 512) {
            float4 v = Wb[i];
            s += v.x * v.x + v.y * v.y + v.z * v.z + v.w * v.w;
        }
        #pragma unroll
        for (int o = 16; o > 0; o >>= 1)
            s += __shfl_xor_sync(0xffffffffu, s, o);
        __shared__ float red[16];
        if ((tid & 31) == 0) red[tid >> 5] = s;
        __syncthreads();
        if (tid == 0) {
            double t = 0.0;
            #pragma unroll
            for (int w = 0; w < 16; ++w) t += (double)red[w];
            g_w2p[b * WX + cx] = t;
        }
    }
}

// ---------------------------------------------------------------------------
// K2: reduce hist partials -> (g_msum, g_mcnt) with 8 sub-reducers per bin.
// grid 64 x 512 = 32768 threads. Block 0 also reduces g_w2p -> g_w2.
// ---------------------------------------------------------------------------
__global__ __launch_bounds__(512) void k2() {
    const int gid = blockIdx.x * 512 + threadIdx.x;   // 0..32767
    const int idx = gid & (NB * NSEG - 1);            // (b, bin)
    const int sub = gid >> 12;                        // 0..7
    const int b   = idx >> 10;
    const int bin = idx & (NSEG - 1);

    float sum = 0.f, cnt = 0.f;
    const int p0 = sub * (HB / 8);
    #pragma unroll
    for (int p = p0; p < p0 + HB / 8; ++p) {          // 16 coalesced float2 loads
        float2 v = g_part2[(size_t)(b * HB + p) * NSEG + bin];
        sum += v.x; cnt += v.y;
    }
    atomicAdd(&g_msum[idx], sum);
    atomicAdd(&g_mcnt[idx], cnt);

    // w2 partial reduction: block 0, warps 0..NB-1
    if (blockIdx.x == 0) {
        const int warp = threadIdx.x >> 5;
        const int lane = threadIdx.x & 31;
        if (warp < NB) {
            double t = (double)0.0 + g_w2p[warp * WX + lane];
            #pragma unroll
            for (int o = 16; o > 0; o >>= 1)
                t += __shfl_xor_sync(0xffffffffu, t, o);
            if (lane == 0) g_w2[warp] = t;
        }
    }
}

// ---------------------------------------------------------------------------
// K3: quad[b] = m^T L m ; last block (counter) computes final loss.
// grid (QX, NB) x 256 (8 warps -> 8 rows each).
// ---------------------------------------------------------------------------
__global__ __launch_bounds__(256) void k3(const float* __restrict__ L,
                                          float* __restrict__ out) {
    __shared__ float s_m[NSEG];
    const int b    = blockIdx.y;
    const int tid  = threadIdx.x;
    const int warp = tid >> 5;
    const int lane = tid & 31;

    for (int i = tid; i < NSEG; i += 256) {
        float c = g_mcnt[b * NSEG + i];
        s_m[i] = (c > 0.f) ? g_msum[b * NSEG + i] / c : 0.f;
    }
    __syncthreads();

    const int r = blockIdx.x * 8 + warp;
    const float4* __restrict__ Lr =
        (const float4*)(L + (size_t)b * NSEG * NSEG + (size_t)r * NSEG);
    const float4* __restrict__ sm4 = (const float4*)s_m;

    float s = 0.f;
    #pragma unroll
    for (int i = 0; i < NSEG / 128; ++i) {            // 8 float4 iters
        int c4 = i * 32 + lane;
        float4 l4 = Lr[c4];
        float4 m4 = sm4[c4];
        s += l4.x * m4.x + l4.y * m4.y + l4.z * m4.z + l4.w * m4.w;
    }
    #pragma unroll
    for (int o = 16; o > 0; o >>= 1)
        s += __shfl_xor_sync(0xffffffffu, s, o);
    if (lane == 0)
        atomicAdd(&g_quad[b], (double)s * (double)s_m[r]);

    __syncthreads();
    if (tid == 0) {
        __threadfence();
        unsigned int prev = atomicAdd(&g_done, 1u);
        if (prev == K3_TOTAL - 1) {
            __threadfence();
            double loss = 0.0;
            #pragma unroll
            for (int k = 0; k < NB; ++k)
                loss += (2.0 / sqrt(g_w2[k])) * ((double)NCH * g_quad[k]);
            out[0] = (float)loss;
        }
    }
}

extern "C" void kernel_launch(void* const* d_in, const int* in_sizes, int n_in,
                              void* d_out, int out_size) {
    const float* pred = (const float*)d_in[0];
    const float* W    = (const float*)d_in[1];
    const float* L    = (const float*)d_in[2];
    const void*  ids  = (const void*)d_in[3];
    float* out = (float*)d_out;

    k1<<<dim3(HB + WX, NB), 512>>>(pred, ids, W);
    k2<<<64, 512>>>();
    k3<<<dim3(QX, NB), 256>>>(L, out);
}

// round 9
// speedup vs baseline: 1.5142x; 1.1568x over previous
#include <cuda_runtime.h>
#include <math.h>

#define NSEG 1024
#define NPIX (512 * 512)
#define NCH  21
#define NB   4
#define HB   128           // K1 x-blocks per batch (512 blocks total = 1 wave)
#define QX   128           // quad x-blocks per batch
#define K3_TOTAL (QX * NB)

// Scratch (no allocations). Slot-overwritten or zeroed in K1 before use.
__device__ float2 g_part2[NB * HB * NSEG];   // hist per-block (sum, cnt) — overwritten
__device__ double g_w2p[NB * HB];            // W^2 per-block partials — overwritten
__device__ float  g_msum[NB * NSEG];         // zeroed in K1, atomics in K2
__device__ float  g_mcnt[NB * NSEG];         // zeroed in K1, atomics in K2
__device__ double g_w2[NB];                  // written (overwrite) in K2
__device__ double g_quad[NB];                // zeroed in K1, atomics in K3
__device__ unsigned int g_done;              // zeroed in K1, counter in K3

// ---------------------------------------------------------------------------
// K1: grid (HB, NB) x 512 — 512 identical blocks, exactly one wave.
// Each block: shared-mem histogram over 2048 px (1 float4-group/thread,
// 21 channel loads) + a 2048-float4 slice of ||W||^2 (4/thread).
// Block x==0 additionally zeroes the downstream accumulators.
// ---------------------------------------------------------------------------
__global__ __launch_bounds__(512) void k1(const float* __restrict__ pred,
                                          const void* __restrict__ ids_v,
                                          const float* __restrict__ W) {
    __shared__ float s_sum[NSEG];
    __shared__ int   s_cnt[NSEG];
    __shared__ int   s_nonzero;
    __shared__ float red[16];

    const int tid = threadIdx.x;
    const int b   = blockIdx.y;
    const int x   = blockIdx.x;

    if (tid == 0) s_nonzero = 0;
    for (int i = tid; i < NSEG; i += 512) { s_sum[i] = 0.f; s_cnt[i] = 0; }
    __syncthreads();

    // dtype probe: int64 ids in [0,1024) -> all odd 32-bit words zero (L2-hot).
    if (tid < 128 && ((const unsigned int*)ids_v)[2 * tid + 1] != 0u)
        atomicOr(&s_nonzero, 1);

    if (x == 0) {   // zero accumulators consumed by K2/K3 (stream-ordered)
        for (int i = tid; i < NSEG; i += 512) {
            g_msum[b * NSEG + i] = 0.f;
            g_mcnt[b * NSEG + i] = 0.f;
        }
        if (tid == 0) {
            g_quad[b] = 0.0;
            if (b == 0) g_done = 0u;
        }
    }
    __syncthreads();
    const int is64 = !s_nonzero;

    // ---- histogram phase ----
    const float4* __restrict__ p4 =
        (const float4*)(pred + (size_t)b * NCH * NPIX);
    const int4* __restrict__ id32v =
        (const int4*)((const int*)ids_v + (size_t)b * NPIX);
    const longlong2* __restrict__ id64v =
        (const longlong2*)((const long long*)ids_v + (size_t)b * NPIX);

    const int q = x * 512 + tid;                     // one float4-group/thread
    float4 acc = make_float4(0.f, 0.f, 0.f, 0.f);
    #pragma unroll
    for (int c = 0; c < NCH; ++c) {
        float4 v = p4[(size_t)c * (NPIX / 4) + q];
        acc.x += v.x; acc.y += v.y; acc.z += v.z; acc.w += v.w;
    }
    int i0, i1, i2, i3;
    if (is64) {
        longlong2 a = id64v[2 * q];
        longlong2 c = id64v[2 * q + 1];
        i0 = (int)a.x; i1 = (int)a.y; i2 = (int)c.x; i3 = (int)c.y;
    } else {
        int4 iv = id32v[q];
        i0 = iv.x; i1 = iv.y; i2 = iv.z; i3 = iv.w;
    }
    atomicAdd(&s_sum[i0 & (NSEG - 1)], acc.x); atomicAdd(&s_cnt[i0 & (NSEG - 1)], 1);
    atomicAdd(&s_sum[i1 & (NSEG - 1)], acc.y); atomicAdd(&s_cnt[i1 & (NSEG - 1)], 1);
    atomicAdd(&s_sum[i2 & (NSEG - 1)], acc.z); atomicAdd(&s_cnt[i2 & (NSEG - 1)], 1);
    atomicAdd(&s_sum[i3 & (NSEG - 1)], acc.w); atomicAdd(&s_cnt[i3 & (NSEG - 1)], 1);

    // ---- W^2 phase (overlaps hist atomics' latency across warps) ----
    const float4* __restrict__ Wb = (const float4*)(W + (size_t)b * NSEG * NSEG);
    float ws = 0.f;
    #pragma unroll
    for (int j = 0; j < 4; ++j) {
        float4 v = Wb[x * 2048 + j * 512 + tid];
        ws += v.x * v.x + v.y * v.y + v.z * v.z + v.w * v.w;
    }
    #pragma unroll
    for (int o = 16; o > 0; o >>= 1)
        ws += __shfl_xor_sync(0xffffffffu, ws, o);
    if ((tid & 31) == 0) red[tid >> 5] = ws;

    __syncthreads();

    // flush hist partials (overwrite slot)
    float2* __restrict__ slot = g_part2 + (size_t)(b * HB + x) * NSEG;
    for (int i = tid; i < NSEG; i += 512)
        slot[i] = make_float2(s_sum[i], (float)s_cnt[i]);

    if (tid == 0) {
        double t = 0.0;
        #pragma unroll
        for (int w = 0; w < 16; ++w) t += (double)red[w];
        g_w2p[b * HB + x] = t;
    }
}

// ---------------------------------------------------------------------------
// K2: reduce hist partials -> (g_msum, g_mcnt) with 8 sub-reducers per bin.
// grid 64 x 512 = 32768 threads. Block 0 also reduces g_w2p -> g_w2.
// ---------------------------------------------------------------------------
__global__ __launch_bounds__(512) void k2() {
    const int gid = blockIdx.x * 512 + threadIdx.x;   // 0..32767
    const int idx = gid & (NB * NSEG - 1);            // (b, bin)
    const int sub = gid >> 12;                        // 0..7
    const int b   = idx >> 10;
    const int bin = idx & (NSEG - 1);

    float sum = 0.f, cnt = 0.f;
    const int p0 = sub * (HB / 8);
    #pragma unroll
    for (int p = p0; p < p0 + HB / 8; ++p) {          // 16 coalesced float2 loads
        float2 v = g_part2[(size_t)(b * HB + p) * NSEG + bin];
        sum += v.x; cnt += v.y;
    }
    atomicAdd(&g_msum[idx], sum);
    atomicAdd(&g_mcnt[idx], cnt);

    // w2 partial reduction: block 0, warps 0..NB-1 (128 partials per batch)
    if (blockIdx.x == 0) {
        const int warp = threadIdx.x >> 5;
        const int lane = threadIdx.x & 31;
        if (warp < NB) {
            double t = 0.0;
            #pragma unroll
            for (int j = 0; j < HB / 32; ++j)         // 4 loads
                t += g_w2p[warp * HB + j * 32 + lane];
            #pragma unroll
            for (int o = 16; o > 0; o >>= 1)
                t += __shfl_xor_sync(0xffffffffu, t, o);
            if (lane == 0) g_w2[warp] = t;
        }
    }
}

// ---------------------------------------------------------------------------
// K3: quad[b] = m^T L m ; last block (counter) computes final loss.
// grid (QX, NB) x 256 (8 warps -> 8 rows each).
// ---------------------------------------------------------------------------
__global__ __launch_bounds__(256) void k3(const float* __restrict__ L,
                                          float* __restrict__ out) {
    __shared__ float s_m[NSEG];
    const int b    = blockIdx.y;
    const int tid  = threadIdx.x;
    const int warp = tid >> 5;
    const int lane = tid & 31;

    for (int i = tid; i < NSEG; i += 256) {
        float c = g_mcnt[b * NSEG + i];
        s_m[i] = (c > 0.f) ? g_msum[b * NSEG + i] / c : 0.f;
    }
    __syncthreads();

    const int r = blockIdx.x * 8 + warp;
    const float4* __restrict__ Lr =
        (const float4*)(L + (size_t)b * NSEG * NSEG + (size_t)r * NSEG);
    const float4* __restrict__ sm4 = (const float4*)s_m;

    float s = 0.f;
    #pragma unroll
    for (int i = 0; i < NSEG / 128; ++i) {            // 8 float4 iters
        int c4 = i * 32 + lane;
        float4 l4 = Lr[c4];
        float4 m4 = sm4[c4];
        s += l4.x * m4.x + l4.y * m4.y + l4.z * m4.z + l4.w * m4.w;
    }
    #pragma unroll
    for (int o = 16; o > 0; o >>= 1)
        s += __shfl_xor_sync(0xffffffffu, s, o);
    if (lane == 0)
        atomicAdd(&g_quad[b], (double)s * (double)s_m[r]);

    __syncthreads();
    if (tid == 0) {
        __threadfence();
        unsigned int prev = atomicAdd(&g_done, 1u);
        if (prev == K3_TOTAL - 1) {
            __threadfence();
            double loss = 0.0;
            #pragma unroll
            for (int k = 0; k < NB; ++k)
                loss += (2.0 / sqrt(g_w2[k])) * ((double)NCH * g_quad[k]);
            out[0] = (float)loss;
        }
    }
}

extern "C" void kernel_launch(void* const* d_in, const int* in_sizes, int n_in,
                              void* d_out, int out_size) {
    const float* pred = (const float*)d_in[0];
    const float* W    = (const float*)d_in[1];
    const float* L    = (const float*)d_in[2];
    const void*  ids  = (const void*)d_in[3];
    float* out = (float*)d_out;

    k1<<<dim3(HB, NB), 512>>>(pred, ids, W);
    k2<<<64, 512>>>();
    k3<<<dim3(QX, NB), 256>>>(L, out);
}